// round 13
// baseline (speedup 1.0000x reference)
#include <cuda_runtime.h>
#include <cstdint>

#define EDIM 512
#define JDIM 1536
#define TLEN 256
#define NBLK 32      // blocks per sentence per layer in the scan
#define POOL 128

// ---------------- scratch layout (floats) ----------------
#define OFF_XA   0
#define OFF_XB   (OFF_XA + 2*TLEN*EDIM)          // layer-0 trace epoch0
#define OFF_XC   (OFF_XB + 2*TLEN*EDIM)          // layer-1 trace epoch0
#define OFF_FIN  (OFF_XC + 2*TLEN*EDIM)          // finals epoch0: [s][l][EDIM]
#define OFF_X2A  (OFF_FIN + 2*2*EDIM)            // layer-0 trace epoch1
#define OFF_X2B  (OFF_X2A + 2*2*EDIM)            // layer-1 trace epoch1
#define OFF_X2C  (OFF_X2B + 2*2*EDIM)            // rnn2 trace
#define OFF_FIN2 (OFF_X2C + 2*2*EDIM)            // finals epoch1: [s][l][EDIM]
#define OFF_SEQ  (OFF_FIN2 + 2*2*EDIM)           // [s][l][POOL]
#define OFF_HT2  (OFF_SEQ + 2*2*POOL)            // [s][EDIM]
#define SCRATCH_SZ (OFF_HT2 + 2*EDIM)

__device__ float d_scratch[SCRATCH_SZ];
// flag regions: [(layer*2+s)][block] — 4 regions x 32 u32 = 4 x 128B lines
__device__ __align__(128) unsigned g_flags[4 * NBLK];

__device__ __forceinline__ float sigf(float x) {
    return __fdividef(1.f, 1.f + __expf(-x));
}

__device__ __forceinline__ void flag_release(unsigned* p, unsigned v) {
    asm volatile("st.release.gpu.global.u32 [%0], %1;" :: "l"(p), "r"(v) : "memory");
}
__device__ __forceinline__ unsigned flag_acquire(const unsigned* p) {
    unsigned v;
    asm volatile("ld.acquire.gpu.global.u32 %0, [%1];" : "=r"(v) : "l"(p) : "memory");
    return v;
}

__device__ __forceinline__ float4 ldcg4(const float4* p) {
    float4 v;
    asm volatile("ld.global.cg.v4.f32 {%0,%1,%2,%3}, [%4];"
                 : "=f"(v.x), "=f"(v.y), "=f"(v.z), "=f"(v.w) : "l"(p));
    return v;
}

// ---------------- embedding gather (zeroes all scan flags each replay) ----------------
__global__ void embed_kernel(float* __restrict__ x, const int* __restrict__ sA,
                             const int* __restrict__ sB, const float* __restrict__ emb) {
    const int t = blockIdx.x, s = blockIdx.y;
    if (t == 0 && s == 0 && threadIdx.x < 4 * NBLK) g_flags[threadIdx.x] = 0u;
    const int idx = (s == 0) ? sA[t] : sB[t];
    const float4* src = reinterpret_cast<const float4*>(emb + (size_t)idx * EDIM);
    float4* dst = reinterpret_cast<float4*>(x + ((size_t)s * TLEN + t) * EDIM);
    dst[threadIdx.x] = src[threadIdx.x];
}

// ---------------- fused pipelined 2-layer GRU scan (all gates on the fly) ----------------
// Template INF4: input dim IN = INF4*64 (8 -> 512, 2 -> 128).
// grid (NBLK, 2 sentences, nlayers). Block owns 16 h-elements; weights in regs
// at k4 = kc + u*16 (matches activation reads).
// Poll+stage merged per-float4: each staging thread acquires the ONE flag
// guarding its float4 (flags[i>>2]), then loads it — a slow producer delays
// only its own consumers' loads; everything else overlaps. Per-location
// release/acquire pairing unchanged from R12.
// flag = base + (#trace rows written); publish: stores -> syncthreads ->
// st.release by tid 0 (R10/R12-proven).
template <int INF4>
__global__ void __launch_bounds__(256, 1) fused_scan_kernel(
    float* __restrict__ x0_trace, float* __restrict__ x1_trace,
    float* __restrict__ hT, int hTs,
    const float* __restrict__ x_in,
    const float* __restrict__ Wih0, const float* __restrict__ bih0,
    const float* __restrict__ Whh0, const float* __restrict__ bhh0,
    const float* __restrict__ Wih1, const float* __restrict__ bih1,
    const float* __restrict__ Whh1, const float* __restrict__ bhh1,
    int L, unsigned base) {
    constexpr int IN = INF4 * 64;
    const int s = blockIdx.y, b = blockIdx.x, layer = blockIdx.z;
    if (INF4 != 8 && layer != 0) return;   // never launched; keeps one code path
    const int tid = threadIdx.x;
    const int e = tid >> 4, kc = tid & 15;
    const int elem = b * 16 + e;
    unsigned* flags0 = g_flags + (0 * 2 + s) * NBLK;
    unsigned* flags1 = g_flags + (2 + s) * NBLK;
    unsigned* myflag = (layer ? flags1 : flags0) + b;
    unsigned* ownflags = layer ? flags1 : flags0;

    const float* Whh = layer ? Whh1 : Whh0;
    const float* bhh = layer ? bhh1 : bhh0;

    // recurrent weights -> registers at k4 = kc + u*16 (hidden dim is always 512)
    float4 wr[8], wz[8], wn[8];
    {
        const float4* Rr = reinterpret_cast<const float4*>(Whh + (size_t)elem * EDIM);
        const float4* Rz = reinterpret_cast<const float4*>(Whh + (size_t)(EDIM + elem) * EDIM);
        const float4* Rn = reinterpret_cast<const float4*>(Whh + (size_t)(2 * EDIM + elem) * EDIM);
#pragma unroll
        for (int u = 0; u < 8; u++) {
            wr[u] = Rr[kc + u * 16];
            wz[u] = Rz[kc + u * 16];
            wn[u] = Rn[kc + u * 16];
        }
    }
    const float bhr = bhh[elem], bhz = bhh[EDIM + elem], bhn = bhh[2 * EDIM + elem];

    // input-gate weights -> registers (input dim IN; layer 1 only exists for IN==512)
    float4 ur[INF4], uz[INF4], un[INF4];
    float bir, biz, bin;
    {
        const float* U  = layer ? Wih1 : Wih0;
        const float* bi = layer ? bih1 : bih0;
        const float4* Ur = reinterpret_cast<const float4*>(U + (size_t)elem * IN);
        const float4* Uz = reinterpret_cast<const float4*>(U + (size_t)(EDIM + elem) * IN);
        const float4* Un = reinterpret_cast<const float4*>(U + (size_t)(2 * EDIM + elem) * IN);
#pragma unroll
        for (int u = 0; u < INF4; u++) {
            ur[u] = Ur[kc + u * 16];
            uz[u] = Uz[kc + u * 16];
            un[u] = Un[kc + u * 16];
        }
        bir = bi[elem]; biz = bi[EDIM + elem]; bin = bi[2 * EDIM + elem];
    }

    __shared__ float sx[IN];      // input x[t]
    __shared__ float shh[EDIM];   // own h[t-1]

    const float* xin = layer ? (x0_trace + (size_t)s * L * EDIM)
                             : (x_in + (size_t)s * L * IN);
    float* xo = (layer ? x1_trace : x0_trace) + (size_t)s * L * EDIM;

    for (int t = 0; t < L; t++) {
        // ---- merged poll + stage ----
        // lower threads: input x[t]. layer 1 waits for x0 row t (flags0 >= base+t+1);
        // layer 0 input is pre-launch-ready.
        if (tid < IN / 4) {
            if (layer) {
                const unsigned tgt = base + (unsigned)t + 1u;
                const unsigned* fp = &flags0[tid >> 2];
                while (flag_acquire(fp) < tgt) { }
            }
            reinterpret_cast<float4*>(sx)[tid] =
                ldcg4(reinterpret_cast<const float4*>(xin + (size_t)t * IN) + tid);
        }
        // upper threads: own h[t-1] (own-layer flags >= base+t)
        if (tid >= 128) {
            const int i = tid - 128;
            if (t > 0) {
                const unsigned tgt = base + (unsigned)t;
                const unsigned* fp = &ownflags[i >> 2];
                while (flag_acquire(fp) < tgt) { }
                reinterpret_cast<float4*>(shh)[i] =
                    ldcg4(reinterpret_cast<const float4*>(xo + (size_t)(t - 1) * EDIM) + i);
            } else {
                reinterpret_cast<float4*>(shh)[i] = make_float4(0.f, 0.f, 0.f, 0.f);
            }
        }
        __syncthreads();

        // matvecs (activation index kc + u*16 == weight-register index)
        float pr = 0.f, pz = 0.f, pn = 0.f;
        float qr = 0.f, qz = 0.f, qn = 0.f;
#pragma unroll
        for (int u = 0; u < 8; u++) {
            const float4 h4 = reinterpret_cast<const float4*>(shh)[kc + u * 16];
            pr += wr[u].x * h4.x; pr += wr[u].y * h4.y; pr += wr[u].z * h4.z; pr += wr[u].w * h4.w;
            pz += wz[u].x * h4.x; pz += wz[u].y * h4.y; pz += wz[u].z * h4.z; pz += wz[u].w * h4.w;
            pn += wn[u].x * h4.x; pn += wn[u].y * h4.y; pn += wn[u].z * h4.z; pn += wn[u].w * h4.w;
        }
#pragma unroll
        for (int u = 0; u < INF4; u++) {
            const float4 x4 = reinterpret_cast<const float4*>(sx)[kc + u * 16];
            qr += ur[u].x * x4.x; qr += ur[u].y * x4.y; qr += ur[u].z * x4.z; qr += ur[u].w * x4.w;
            qz += uz[u].x * x4.x; qz += uz[u].y * x4.y; qz += uz[u].z * x4.z; qz += uz[u].w * x4.w;
            qn += un[u].x * x4.x; qn += un[u].y * x4.y; qn += un[u].z * x4.z; qn += un[u].w * x4.w;
        }
        // reductions over the 16-lane group
        float sr = pr + qr, sz = pz + qz;
#pragma unroll
        for (int off = 8; off > 0; off >>= 1) {
            sr += __shfl_down_sync(0xffffffffu, sr, off, 16);
            sz += __shfl_down_sync(0xffffffffu, sz, off, 16);
            pn += __shfl_down_sync(0xffffffffu, pn, off, 16);
            qn += __shfl_down_sync(0xffffffffu, qn, off, 16);
        }
        if (kc == 0) {
            const float hold = shh[elem];
            const float r = sigf(sr + bir + bhr);
            const float z = sigf(sz + biz + bhz);
            const float n = tanhf(qn + bin + r * (pn + bhn));
            const float hnew = (1.f - z) * n + z * hold;
            __stcg(xo + (size_t)t * EDIM + elem, hnew);
            if (t == L - 1) hT[s * hTs + layer * EDIM + elem] = hnew;
        }
        __syncthreads();
        if (tid == 0) flag_release(myflag, base + (unsigned)t + 1u);
    }
}

// ---------------- conv1d(stride2,pad255) + bias + global maxpool ----------------
__global__ void conv_pool_kernel(float* __restrict__ seq, const float* __restrict__ hin,
                                 const float* __restrict__ cw, const float* __restrict__ cb) {
    const int s = blockIdx.x >> 1, oc = blockIdx.x & 1;
    __shared__ float sin[2 * EDIM];
    __shared__ float sw[2 * EDIM];
    __shared__ float red[256];
    const int tid = threadIdx.x;
    for (int i = tid; i < 2 * EDIM; i += 256) {
        sin[i] = hin[(size_t)s * 2 * EDIM + i];
        sw[i]  = cw[(size_t)oc * 2 * EDIM + i];
    }
    __syncthreads();
    const int base = 2 * tid - 255;
    const int k0 = (base < 0) ? -base : 0;
    const int k1 = EDIM - ((base > 0) ? base : 0);
    // 4-way accumulator split — breaks the serial FFMA dependency chain
    float v0 = 0.f, v1 = 0.f, v2 = 0.f, v3 = 0.f;
    int k = k0;
    for (; k + 3 < k1; k += 4) {
        v0 += sw[k]     * sin[base + k]     + sw[EDIM + k]     * sin[EDIM + base + k];
        v1 += sw[k + 1] * sin[base + k + 1] + sw[EDIM + k + 1] * sin[EDIM + base + k + 1];
        v2 += sw[k + 2] * sin[base + k + 2] + sw[EDIM + k + 2] * sin[EDIM + base + k + 2];
        v3 += sw[k + 3] * sin[base + k + 3] + sw[EDIM + k + 3] * sin[EDIM + base + k + 3];
    }
    for (; k < k1; k++)
        v0 += sw[k] * sin[base + k] + sw[EDIM + k] * sin[EDIM + base + k];
    red[tid] = cb[oc] + (v0 + v1) + (v2 + v3);
    __syncthreads();
    for (int off = 128; off > 0; off >>= 1) {
        if (tid < off) red[tid] = fmaxf(red[tid], red[tid + off]);
        __syncthreads();
    }
    const float M = red[0];
    if (tid < POOL) seq[((size_t)s * 2 + oc) * POOL + tid] = M;
}

// ---------------- head ----------------
__global__ void head_kernel(float* __restrict__ out, const float* __restrict__ hT2,
                            const float* __restrict__ WA, const float* __restrict__ WB,
                            const float* __restrict__ b_bi, const float* __restrict__ Wlin,
                            const float* __restrict__ blin) {
    const int j = threadIdx.x;
    __shared__ float shx[EDIM];
    __shared__ float shv[EDIM];
    __shared__ float red[256];
    for (int k = j; k < EDIM; k += 256) {
        const float a = hT2[k], b = hT2[EDIM + k];
        shx[k] = a * b;
        shv[k] = fabsf(a - b);
    }
    __syncthreads();
    // 4-way accumulator split
    float a0 = 0.f, a1 = 0.f, a2 = 0.f, a3 = 0.f;
    for (int k = 0; k < EDIM; k += 4) {
        a0 += shx[k]     * WA[(size_t)k * 256 + j]       + shv[k]     * WB[(size_t)k * 256 + j];
        a1 += shx[k + 1] * WA[(size_t)(k + 1) * 256 + j] + shv[k + 1] * WB[(size_t)(k + 1) * 256 + j];
        a2 += shx[k + 2] * WA[(size_t)(k + 2) * 256 + j] + shv[k + 2] * WB[(size_t)(k + 2) * 256 + j];
        a3 += shx[k + 3] * WA[(size_t)(k + 3) * 256 + j] + shv[k + 3] * WB[(size_t)(k + 3) * 256 + j];
    }
    const float acc = b_bi[j] + (a0 + a1) + (a2 + a3);
    const float ht = tanhf(acc);
    red[j] = ht * Wlin[j];
    __syncthreads();
    for (int off = 128; off > 0; off >>= 1) {
        if (j < off) red[j] += red[j + off];
        __syncthreads();
    }
    if (j == 0) out[0] = 1.f / (1.f + __expf(-(red[0] + blin[0])));
}

// ---------------- launch ----------------
extern "C" void kernel_launch(void* const* d_in, const int* in_sizes, int n_in,
                              void* d_out, int out_size) {
    const int*   sentA  = (const int*)  d_in[0];
    const int*   sentB  = (const int*)  d_in[1];
    const float* emb    = (const float*)d_in[2];
    const float* Wih1   = (const float*)d_in[3];
    const float* Whh1   = (const float*)d_in[4];
    const float* bih1   = (const float*)d_in[5];
    const float* bhh1   = (const float*)d_in[6];
    const float* conv_w = (const float*)d_in[7];
    const float* conv_b = (const float*)d_in[8];
    const float* Wih2   = (const float*)d_in[9];
    const float* Whh2   = (const float*)d_in[10];
    const float* bih2   = (const float*)d_in[11];
    const float* bhh2   = (const float*)d_in[12];
    const float* WA     = (const float*)d_in[13];
    const float* WB     = (const float*)d_in[14];
    const float* b_bi   = (const float*)d_in[15];
    const float* W_lin  = (const float*)d_in[16];
    const float* b_lin  = (const float*)d_in[17];
    float* out = (float*)d_out;

    float* S = nullptr;
    cudaGetSymbolAddress((void**)&S, d_scratch);

    float* xA   = S + OFF_XA;
    float* xB   = S + OFF_XB;
    float* xC   = S + OFF_XC;
    float* fin  = S + OFF_FIN;
    float* x2a  = S + OFF_X2A;
    float* x2b  = S + OFF_X2B;
    float* x2c  = S + OFF_X2C;
    float* fin2 = S + OFF_FIN2;
    float* seq  = S + OFF_SEQ;
    float* hT2  = S + OFF_HT2;

    const size_t WSTRIDE = (size_t)JDIM * EDIM;

    // embedding (zeroes flags each replay)
    embed_kernel<<<dim3(TLEN, 2), 128>>>(xA, sentA, sentB, emb);

    // ---- epoch 0: pipelined 2-layer scan, both layers fly ----
    fused_scan_kernel<8><<<dim3(NBLK, 2, 2), 256>>>(
        xB, xC, fin, 2 * EDIM,
        xA,
        Wih1, bih1, Whh1, bhh1,
        Wih1 + WSTRIDE, bih1 + JDIM, Whh1 + WSTRIDE, bhh1 + JDIM,
        TLEN, 0u);

    // ---- epoch 1 (L = 2): both layers fly from fin ----
    fused_scan_kernel<8><<<dim3(NBLK, 2, 2), 256>>>(
        x2a, x2b, fin2, 2 * EDIM,
        fin,
        Wih1, bih1, Whh1, bhh1,
        Wih1 + WSTRIDE, bih1 + JDIM, Whh1 + WSTRIDE, bhh1 + JDIM,
        2, (unsigned)TLEN);

    // conv + pool
    conv_pool_kernel<<<4, 256>>>(seq, fin2, conv_w, conv_b);

    // rnn_second (single layer, L = 2, input dim 128, gates on the fly)
    fused_scan_kernel<2><<<dim3(NBLK, 2, 1), 256>>>(
        x2c, x2c, hT2, EDIM,
        seq,
        Wih2, bih2, Whh2, bhh2,
        Wih2, bih2, Whh2, bhh2,
        2, (unsigned)TLEN + 2u);

    // head
    head_kernel<<<1, 256>>>(out, hT2, WA, WB, b_bi, W_lin, b_lin);
}

// round 14
// speedup vs baseline: 2.4484x; 2.4484x over previous
#include <cuda_runtime.h>
#include <cstdint>

#define EDIM 512
#define JDIM 1536
#define TLEN 256
#define NBLK 32      // blocks per sentence per layer in the scan
#define POOL 128

// ---------------- scratch layout (floats) ----------------
#define OFF_XA   0
#define OFF_XB   (OFF_XA + 2*TLEN*EDIM)          // layer-0 trace epoch0
#define OFF_XC   (OFF_XB + 2*TLEN*EDIM)          // layer-1 trace epoch0
#define OFF_FIN  (OFF_XC + 2*TLEN*EDIM)          // finals epoch0: [s][l][EDIM]
#define OFF_X2A  (OFF_FIN + 2*2*EDIM)            // layer-0 trace epoch1
#define OFF_X2B  (OFF_X2A + 2*2*EDIM)            // layer-1 trace epoch1
#define OFF_X2C  (OFF_X2B + 2*2*EDIM)            // rnn2 trace
#define OFF_FIN2 (OFF_X2C + 2*2*EDIM)            // finals epoch1: [s][l][EDIM]
#define OFF_SEQ  (OFF_FIN2 + 2*2*EDIM)           // [s][l][POOL]
#define OFF_HT2  (OFF_SEQ + 2*2*POOL)            // [s][EDIM]
#define SCRATCH_SZ (OFF_HT2 + 2*EDIM)

__device__ float d_scratch[SCRATCH_SZ];
// flag regions: [(layer*2+s)][block] — 4 regions x 32 u32 = 4 x 128B lines
__device__ __align__(128) unsigned g_flags[4 * NBLK];

__device__ __forceinline__ float sigf(float x) {
    return __fdividef(1.f, 1.f + __expf(-x));
}

__device__ __forceinline__ void flag_release(unsigned* p, unsigned v) {
    asm volatile("st.release.gpu.global.u32 [%0], %1;" :: "l"(p), "r"(v) : "memory");
}
__device__ __forceinline__ unsigned flag_acquire(const unsigned* p) {
    unsigned v;
    asm volatile("ld.acquire.gpu.global.u32 %0, [%1];" : "=r"(v) : "l"(p) : "memory");
    return v;
}

__device__ __forceinline__ float4 ldcg4(const float4* p) {
    float4 v;
    asm volatile("ld.global.cg.v4.f32 {%0,%1,%2,%3}, [%4];"
                 : "=f"(v.x), "=f"(v.y), "=f"(v.z), "=f"(v.w) : "l"(p));
    return v;
}

// ---------------- embedding gather (zeroes all scan flags each replay) ----------------
__global__ void embed_kernel(float* __restrict__ x, const int* __restrict__ sA,
                             const int* __restrict__ sB, const float* __restrict__ emb) {
    const int t = blockIdx.x, s = blockIdx.y;
    if (t == 0 && s == 0 && threadIdx.x < 4 * NBLK) g_flags[threadIdx.x] = 0u;
    const int idx = (s == 0) ? sA[t] : sB[t];
    const float4* src = reinterpret_cast<const float4*>(emb + (size_t)idx * EDIM);
    float4* dst = reinterpret_cast<float4*>(x + ((size_t)s * TLEN + t) * EDIM);
    dst[threadIdx.x] = src[threadIdx.x];
}

// ---------------- fused pipelined 2-layer GRU scan (all gates on the fly) ----------------
// EXACT R12 version (the 670 µs kernel). Poll concurrency kept minimal:
// only tid<NBLK (layer 0) / tid<2*NBLK (layer 1) spin on the flag lines.
// Template INF4: input dim IN = INF4*64 (8 -> 512, 2 -> 128).
template <int INF4>
__global__ void __launch_bounds__(256, 1) fused_scan_kernel(
    float* __restrict__ x0_trace, float* __restrict__ x1_trace,
    float* __restrict__ hT, int hTs,
    const float* __restrict__ x_in,
    const float* __restrict__ Wih0, const float* __restrict__ bih0,
    const float* __restrict__ Whh0, const float* __restrict__ bhh0,
    const float* __restrict__ Wih1, const float* __restrict__ bih1,
    const float* __restrict__ Whh1, const float* __restrict__ bhh1,
    int L, unsigned base) {
    constexpr int IN = INF4 * 64;
    const int s = blockIdx.y, b = blockIdx.x, layer = blockIdx.z;
    if (INF4 != 8 && layer != 0) return;   // never launched; keeps one code path
    const int tid = threadIdx.x;
    const int e = tid >> 4, kc = tid & 15;
    const int elem = b * 16 + e;
    unsigned* flags0 = g_flags + (0 * 2 + s) * NBLK;
    unsigned* flags1 = g_flags + (2 + s) * NBLK;
    unsigned* myflag = (layer ? flags1 : flags0) + b;

    const float* Whh = layer ? Whh1 : Whh0;
    const float* bhh = layer ? bhh1 : bhh0;

    // recurrent weights -> registers at k4 = kc + u*16 (hidden dim is always 512)
    float4 wr[8], wz[8], wn[8];
    {
        const float4* Rr = reinterpret_cast<const float4*>(Whh + (size_t)elem * EDIM);
        const float4* Rz = reinterpret_cast<const float4*>(Whh + (size_t)(EDIM + elem) * EDIM);
        const float4* Rn = reinterpret_cast<const float4*>(Whh + (size_t)(2 * EDIM + elem) * EDIM);
#pragma unroll
        for (int u = 0; u < 8; u++) {
            wr[u] = Rr[kc + u * 16];
            wz[u] = Rz[kc + u * 16];
            wn[u] = Rn[kc + u * 16];
        }
    }
    const float bhr = bhh[elem], bhz = bhh[EDIM + elem], bhn = bhh[2 * EDIM + elem];

    // input-gate weights -> registers (input dim IN; layer 1 only exists for IN==512)
    float4 ur[INF4], uz[INF4], un[INF4];
    float bir, biz, bin;
    {
        const float* U  = layer ? Wih1 : Wih0;
        const float* bi = layer ? bih1 : bih0;
        const float4* Ur = reinterpret_cast<const float4*>(U + (size_t)elem * IN);
        const float4* Uz = reinterpret_cast<const float4*>(U + (size_t)(EDIM + elem) * IN);
        const float4* Un = reinterpret_cast<const float4*>(U + (size_t)(2 * EDIM + elem) * IN);
#pragma unroll
        for (int u = 0; u < INF4; u++) {
            ur[u] = Ur[kc + u * 16];
            uz[u] = Uz[kc + u * 16];
            un[u] = Un[kc + u * 16];
        }
        bir = bi[elem]; biz = bi[EDIM + elem]; bin = bi[2 * EDIM + elem];
    }

    __shared__ float sx[IN];      // input x[t]
    __shared__ float shh[EDIM];   // own h[t-1]

    const float* xin = layer ? (x0_trace + (size_t)s * L * EDIM)
                             : (x_in + (size_t)s * L * IN);
    float* xo = (layer ? x1_trace : x0_trace) + (size_t)s * L * EDIM;

    for (int t = 0; t < L; t++) {
        // spin phase (R7/R12 protocol, exact — minimal poller count)
        if (layer) {
            if (tid < NBLK) {
                const unsigned* fp = &flags0[tid];
                const unsigned tgt = base + (unsigned)t + 1u;    // x0 row t ready
                while (flag_acquire(fp) < tgt) { }
            } else if (tid < 2 * NBLK && t > 0) {
                const unsigned* fp = &flags1[tid - NBLK];
                const unsigned tgt = base + (unsigned)t;         // own row t-1 ready
                while (flag_acquire(fp) < tgt) { }
            }
        } else if (t > 0 && tid < NBLK) {
            const unsigned* fp = &flags0[tid];
            const unsigned tgt = base + (unsigned)t;
            while (flag_acquire(fp) < tgt) { }
        }
        __syncthreads();
        // stage input x (lower threads) and own h (upper threads)
        if (tid < IN / 4)
            reinterpret_cast<float4*>(sx)[tid] =
                ldcg4(reinterpret_cast<const float4*>(xin + (size_t)t * IN) + tid);
        if (tid >= 128) {
            const int i = tid - 128;
            if (t > 0)
                reinterpret_cast<float4*>(shh)[i] =
                    ldcg4(reinterpret_cast<const float4*>(xo + (size_t)(t - 1) * EDIM) + i);
            else
                reinterpret_cast<float4*>(shh)[i] = make_float4(0.f, 0.f, 0.f, 0.f);
        }
        __syncthreads();

        // matvecs (activation index kc + u*16 == weight-register index)
        float pr = 0.f, pz = 0.f, pn = 0.f;
        float qr = 0.f, qz = 0.f, qn = 0.f;
#pragma unroll
        for (int u = 0; u < 8; u++) {
            const float4 h4 = reinterpret_cast<const float4*>(shh)[kc + u * 16];
            pr += wr[u].x * h4.x; pr += wr[u].y * h4.y; pr += wr[u].z * h4.z; pr += wr[u].w * h4.w;
            pz += wz[u].x * h4.x; pz += wz[u].y * h4.y; pz += wz[u].z * h4.z; pz += wz[u].w * h4.w;
            pn += wn[u].x * h4.x; pn += wn[u].y * h4.y; pn += wn[u].z * h4.z; pn += wn[u].w * h4.w;
        }
#pragma unroll
        for (int u = 0; u < INF4; u++) {
            const float4 x4 = reinterpret_cast<const float4*>(sx)[kc + u * 16];
            qr += ur[u].x * x4.x; qr += ur[u].y * x4.y; qr += ur[u].z * x4.z; qr += ur[u].w * x4.w;
            qz += uz[u].x * x4.x; qz += uz[u].y * x4.y; qz += uz[u].z * x4.z; qz += uz[u].w * x4.w;
            qn += un[u].x * x4.x; qn += un[u].y * x4.y; qn += un[u].z * x4.z; qn += un[u].w * x4.w;
        }
        // reductions over the 16-lane group
        float sr = pr + qr, sz = pz + qz;
#pragma unroll
        for (int off = 8; off > 0; off >>= 1) {
            sr += __shfl_down_sync(0xffffffffu, sr, off, 16);
            sz += __shfl_down_sync(0xffffffffu, sz, off, 16);
            pn += __shfl_down_sync(0xffffffffu, pn, off, 16);
            qn += __shfl_down_sync(0xffffffffu, qn, off, 16);
        }
        if (kc == 0) {
            const float hold = shh[elem];
            const float r = sigf(sr + bir + bhr);
            const float z = sigf(sz + biz + bhz);
            const float n = tanhf(qn + bin + r * (pn + bhn));
            const float hnew = (1.f - z) * n + z * hold;
            __stcg(xo + (size_t)t * EDIM + elem, hnew);
            if (t == L - 1) hT[s * hTs + layer * EDIM + elem] = hnew;
        }
        __syncthreads();
        if (tid == 0) flag_release(myflag, base + (unsigned)t + 1u);
    }
}

// ---------------- conv1d(stride2,pad255) + bias + global maxpool ----------------
// Zero-padded smem input ([2][1040], data at +256) removes the per-iteration
// bounds test/branch; 4 accumulators break the FFMA dependency chain.
#define CPAD 1040
__global__ void conv_pool_kernel(float* __restrict__ seq, const float* __restrict__ hin,
                                 const float* __restrict__ cw, const float* __restrict__ cb) {
    const int s = blockIdx.x >> 1, oc = blockIdx.x & 1;
    __shared__ float spad[2 * CPAD];      // zero-padded input rows
    __shared__ float sw[2 * EDIM];
    __shared__ float red[256];
    const int tid = threadIdx.x;
    for (int i = tid; i < 2 * CPAD; i += 256) spad[i] = 0.f;
    for (int i = tid; i < 2 * EDIM; i += 256)
        sw[i] = cw[(size_t)oc * 2 * EDIM + i];
    __syncthreads();
    for (int i = tid; i < 2 * EDIM; i += 256) {
        const int c = i >> 9, k = i & 511;
        spad[c * CPAD + 256 + k] = hin[(size_t)s * 2 * EDIM + i];
    }
    __syncthreads();
    const int base = 256 + 2 * tid - 255;       // padded index of pos for k=0
    const float* p0 = spad + base;
    const float* p1 = spad + CPAD + base;
    float v0 = 0.f, v1 = 0.f, v2 = 0.f, v3 = 0.f;
#pragma unroll 4
    for (int k = 0; k < EDIM; k += 4) {
        v0 += sw[k]     * p0[k]     + sw[EDIM + k]     * p1[k];
        v1 += sw[k + 1] * p0[k + 1] + sw[EDIM + k + 1] * p1[k + 1];
        v2 += sw[k + 2] * p0[k + 2] + sw[EDIM + k + 2] * p1[k + 2];
        v3 += sw[k + 3] * p0[k + 3] + sw[EDIM + k + 3] * p1[k + 3];
    }
    red[tid] = cb[oc] + (v0 + v1) + (v2 + v3);
    __syncthreads();
    for (int off = 128; off > 0; off >>= 1) {
        if (tid < off) red[tid] = fmaxf(red[tid], red[tid + off]);
        __syncthreads();
    }
    const float M = red[0];
    if (tid < POOL) seq[((size_t)s * 2 + oc) * POOL + tid] = M;
}

// ---------------- head (R12 exact) ----------------
__global__ void head_kernel(float* __restrict__ out, const float* __restrict__ hT2,
                            const float* __restrict__ WA, const float* __restrict__ WB,
                            const float* __restrict__ b_bi, const float* __restrict__ Wlin,
                            const float* __restrict__ blin) {
    const int j = threadIdx.x;
    __shared__ float shx[EDIM];
    __shared__ float shv[EDIM];
    __shared__ float red[256];
    for (int k = j; k < EDIM; k += 256) {
        const float a = hT2[k], b = hT2[EDIM + k];
        shx[k] = a * b;
        shv[k] = fabsf(a - b);
    }
    __syncthreads();
    float acc = b_bi[j];
    for (int k = 0; k < EDIM; k++)
        acc += shx[k] * WA[(size_t)k * 256 + j] + shv[k] * WB[(size_t)k * 256 + j];
    const float ht = tanhf(acc);
    red[j] = ht * Wlin[j];
    __syncthreads();
    for (int off = 128; off > 0; off >>= 1) {
        if (j < off) red[j] += red[j + off];
        __syncthreads();
    }
    if (j == 0) out[0] = 1.f / (1.f + __expf(-(red[0] + blin[0])));
}

// ---------------- launch (R12 exact) ----------------
extern "C" void kernel_launch(void* const* d_in, const int* in_sizes, int n_in,
                              void* d_out, int out_size) {
    const int*   sentA  = (const int*)  d_in[0];
    const int*   sentB  = (const int*)  d_in[1];
    const float* emb    = (const float*)d_in[2];
    const float* Wih1   = (const float*)d_in[3];
    const float* Whh1   = (const float*)d_in[4];
    const float* bih1   = (const float*)d_in[5];
    const float* bhh1   = (const float*)d_in[6];
    const float* conv_w = (const float*)d_in[7];
    const float* conv_b = (const float*)d_in[8];
    const float* Wih2   = (const float*)d_in[9];
    const float* Whh2   = (const float*)d_in[10];
    const float* bih2   = (const float*)d_in[11];
    const float* bhh2   = (const float*)d_in[12];
    const float* WA     = (const float*)d_in[13];
    const float* WB     = (const float*)d_in[14];
    const float* b_bi   = (const float*)d_in[15];
    const float* W_lin  = (const float*)d_in[16];
    const float* b_lin  = (const float*)d_in[17];
    float* out = (float*)d_out;

    float* S = nullptr;
    cudaGetSymbolAddress((void**)&S, d_scratch);

    float* xA   = S + OFF_XA;
    float* xB   = S + OFF_XB;
    float* xC   = S + OFF_XC;
    float* fin  = S + OFF_FIN;
    float* x2a  = S + OFF_X2A;
    float* x2b  = S + OFF_X2B;
    float* x2c  = S + OFF_X2C;
    float* fin2 = S + OFF_FIN2;
    float* seq  = S + OFF_SEQ;
    float* hT2  = S + OFF_HT2;

    const size_t WSTRIDE = (size_t)JDIM * EDIM;

    // embedding (zeroes flags each replay)
    embed_kernel<<<dim3(TLEN, 2), 128>>>(xA, sentA, sentB, emb);

    // ---- epoch 0: pipelined 2-layer scan, both layers fly ----
    fused_scan_kernel<8><<<dim3(NBLK, 2, 2), 256>>>(
        xB, xC, fin, 2 * EDIM,
        xA,
        Wih1, bih1, Whh1, bhh1,
        Wih1 + WSTRIDE, bih1 + JDIM, Whh1 + WSTRIDE, bhh1 + JDIM,
        TLEN, 0u);

    // ---- epoch 1 (L = 2): both layers fly from fin ----
    fused_scan_kernel<8><<<dim3(NBLK, 2, 2), 256>>>(
        x2a, x2b, fin2, 2 * EDIM,
        fin,
        Wih1, bih1, Whh1, bhh1,
        Wih1 + WSTRIDE, bih1 + JDIM, Whh1 + WSTRIDE, bhh1 + JDIM,
        2, (unsigned)TLEN);

    // conv + pool
    conv_pool_kernel<<<4, 256>>>(seq, fin2, conv_w, conv_b);

    // rnn_second (single layer, L = 2, input dim 128, gates on the fly)
    fused_scan_kernel<2><<<dim3(NBLK, 2, 1), 256>>>(
        x2c, x2c, hT2, EDIM,
        seq,
        Wih2, bih2, Whh2, bhh2,
        Wih2, bih2, Whh2, bhh2,
        2, (unsigned)TLEN + 2u);

    // head
    head_kernel<<<1, 256>>>(out, hT2, WA, WB, b_bi, W_lin, b_lin);
}